// round 1
// baseline (speedup 1.0000x reference)
#include <cuda_runtime.h>

#define NN 8192
#define RPB 8
#define MV_TPB 256

// ---------------- device scratch (no allocations allowed) ----------------
__device__ __align__(16) float g_y1[NN], g_y2[NN];
__device__ __align__(16) float g_g1[NN], g_g2[NN];
__device__ __align__(16) float g_z1[NN], g_z2[NN];
__device__ __align__(16) float g_f0[NN], g_f1[NN];
__device__ __align__(16) float g_u0[NN], g_u1[NN];
__device__ __align__(16) float g_g3[NN], g_z3[NN];
__device__ float g_stats[12];   // 6 BN stages x (sum, sumsq)

__global__ void zero_stats_kernel() {
    if (threadIdx.x < 12) g_stats[threadIdx.x] = 0.f;
}

__device__ __forceinline__ void block_atomic_stats(float s, float s2, float* dst) {
#pragma unroll
    for (int o = 16; o > 0; o >>= 1) {
        s  += __shfl_xor_sync(0xffffffffu, s,  o);
        s2 += __shfl_xor_sync(0xffffffffu, s2, o);
    }
    __shared__ float sh[2][8];
    int w = threadIdx.x >> 5;
    if ((threadIdx.x & 31) == 0) { sh[0][w] = s; sh[1][w] = s2; }
    __syncthreads();
    if (threadIdx.x == 0) {
        float a = 0.f, b = 0.f;
        int nw = blockDim.x >> 5;
        for (int i = 0; i < nw; i++) { a += sh[0][i]; b += sh[1][i]; }
        atomicAdd(dst, a);
        atomicAdd(dst + 1, b);
    }
}

__device__ __forceinline__ float2 load_bn(int slot, float cnt) {
    float m = g_stats[2 * slot] / cnt;
    float v = g_stats[2 * slot + 1] / cnt - m * m;
    return make_float2(m, rsqrtf(v + 1e-5f));
}

// ---------------- matvec, 1 column, dual-matrix via blockIdx.z ----------------
__global__ __launch_bounds__(MV_TPB) void mv_c1(
    const float* __restrict__ A0, const float* __restrict__ A1,
    const float* __restrict__ x0, const float* __restrict__ x1,
    float* __restrict__ y0, float* __restrict__ y1, int reverse)
{
    __shared__ float4 xs[NN / 4];
    __shared__ float red[MV_TPB / 32];
    const float* A  = blockIdx.z ? A1 : A0;
    const float* xp = blockIdx.z ? x1 : x0;
    float*       yp = blockIdx.z ? y1 : y0;
    int tid = threadIdx.x;
    const float4* x4 = (const float4*)xp;
#pragma unroll
    for (int k = 0; k < NN / 4 / MV_TPB; k++) xs[tid + k * MV_TPB] = x4[tid + k * MV_TPB];
    __syncthreads();

    int rbase = blockIdx.x * RPB;
    for (int r = 0; r < RPB; r++) {
        int row = rbase + r;
        if (reverse) row = NN - 1 - row;
        const float4* a4 = (const float4*)(A + (size_t)row * NN);
        float acc = 0.f;
#pragma unroll
        for (int k = 0; k < NN / 4 / MV_TPB; k++) {
            float4 av = a4[tid + k * MV_TPB];
            float4 xv = xs[tid + k * MV_TPB];
            acc = fmaf(av.x, xv.x, acc);
            acc = fmaf(av.y, xv.y, acc);
            acc = fmaf(av.z, xv.z, acc);
            acc = fmaf(av.w, xv.w, acc);
        }
#pragma unroll
        for (int o = 16; o > 0; o >>= 1) acc += __shfl_xor_sync(0xffffffffu, acc, o);
        if ((tid & 31) == 0) red[tid >> 5] = acc;
        __syncthreads();
        if (tid == 0) {
            float t = 0.f;
#pragma unroll
            for (int i = 0; i < MV_TPB / 32; i++) t += red[i];
            yp[row] = t;
        }
        __syncthreads();
    }
}

// ---------------- matvec, 2 columns (SoA shared, conflict-free) ----------------
__global__ __launch_bounds__(MV_TPB) void mv_c2(
    const float* __restrict__ A,
    const float* __restrict__ x0, const float* __restrict__ x1,
    float* __restrict__ y0, float* __restrict__ y1, int reverse)
{
    extern __shared__ float shd[];
    float4* xs0 = (float4*)shd;
    float4* xs1 = (float4*)(shd + NN);
    __shared__ float red[2][MV_TPB / 32];
    int tid = threadIdx.x;
    const float4* x04 = (const float4*)x0;
    const float4* x14 = (const float4*)x1;
#pragma unroll
    for (int k = 0; k < NN / 4 / MV_TPB; k++) {
        xs0[tid + k * MV_TPB] = x04[tid + k * MV_TPB];
        xs1[tid + k * MV_TPB] = x14[tid + k * MV_TPB];
    }
    __syncthreads();

    int rbase = blockIdx.x * RPB;
    for (int r = 0; r < RPB; r++) {
        int row = rbase + r;
        if (reverse) row = NN - 1 - row;
        const float4* a4 = (const float4*)(A + (size_t)row * NN);
        float acc0 = 0.f, acc1 = 0.f;
#pragma unroll
        for (int k = 0; k < NN / 4 / MV_TPB; k++) {
            float4 av = a4[tid + k * MV_TPB];
            float4 v0 = xs0[tid + k * MV_TPB];
            float4 v1 = xs1[tid + k * MV_TPB];
            acc0 = fmaf(av.x, v0.x, acc0); acc0 = fmaf(av.y, v0.y, acc0);
            acc0 = fmaf(av.z, v0.z, acc0); acc0 = fmaf(av.w, v0.w, acc0);
            acc1 = fmaf(av.x, v1.x, acc1); acc1 = fmaf(av.y, v1.y, acc1);
            acc1 = fmaf(av.z, v1.z, acc1); acc1 = fmaf(av.w, v1.w, acc1);
        }
#pragma unroll
        for (int o = 16; o > 0; o >>= 1) {
            acc0 += __shfl_xor_sync(0xffffffffu, acc0, o);
            acc1 += __shfl_xor_sync(0xffffffffu, acc1, o);
        }
        if ((tid & 31) == 0) { red[0][tid >> 5] = acc0; red[1][tid >> 5] = acc1; }
        __syncthreads();
        if (tid == 0) {
            float t0 = 0.f, t1 = 0.f;
#pragma unroll
            for (int i = 0; i < MV_TPB / 32; i++) { t0 += red[0][i]; t1 += red[1][i]; }
            y0[row] = t0;
            y1[row] = t1;
        }
        __syncthreads();
    }
}

// ---------------- BN stats over relu(y*w_c + b_c), c=0..3 ([N,4]) ----------------
__global__ void stats_mat4(const float* __restrict__ y,
                           const float* __restrict__ w,
                           const float* __restrict__ b, int slot)
{
    float w0 = w[0], w1 = w[1], w2 = w[2], w3 = w[3];
    float b0 = b[0], b1 = b[1], b2 = b[2], b3 = b[3];
    float s = 0.f, s2 = 0.f;
    for (int j = blockIdx.x * blockDim.x + threadIdx.x; j < NN; j += gridDim.x * blockDim.x) {
        float yv = y[j];
        float v0 = fmaxf(fmaf(yv, w0, b0), 0.f);
        float v1 = fmaxf(fmaf(yv, w1, b1), 0.f);
        float v2 = fmaxf(fmaf(yv, w2, b2), 0.f);
        float v3 = fmaxf(fmaf(yv, w3, b3), 0.f);
        s  += v0 + v1 + v2 + v3;
        s2 += v0 * v0 + v1 * v1 + v2 * v2 + v3 * v3;
    }
    block_atomic_stats(s, s2, &g_stats[2 * slot]);
}

// ---------------- BN stats over relu(z + b) ([N,1]) ----------------
__global__ void stats_vec(const float* __restrict__ z, const float* __restrict__ b, int slot)
{
    float bb = b[0];
    float s = 0.f, s2 = 0.f;
    for (int j = blockIdx.x * blockDim.x + threadIdx.x; j < NN; j += gridDim.x * blockDim.x) {
        float v = fmaxf(z[j] + bb, 0.f);
        s += v; s2 += v * v;
    }
    block_atomic_stats(s, s2, &g_stats[2 * slot]);
}

// ---------------- BN stats for concat block ([N,4] from 2 inputs) ----------------
__global__ void stats_c1(const float* __restrict__ u0, const float* __restrict__ u1,
                         const float* __restrict__ wc1, const float* __restrict__ bc1, int slot)
{
    float s = 0.f, s2 = 0.f;
    for (int j = blockIdx.x * blockDim.x + threadIdx.x; j < NN; j += gridDim.x * blockDim.x) {
        float a = u0[j], b = u1[j];
#pragma unroll
        for (int c = 0; c < 4; c++) {
            float v = fmaxf(a * wc1[c] + b * wc1[4 + c] + bc1[c], 0.f);
            s += v; s2 += v * v;
        }
    }
    block_atomic_stats(s, s2, &g_stats[2 * slot]);
}

// ---------------- g_j = sum_c w2[c] * BN(relu(y*w1_c + b1_c)) ----------------
__global__ void prep_g(const float* __restrict__ y,
                       const float* __restrict__ w1, const float* __restrict__ b1,
                       const float* __restrict__ w2,
                       const float* __restrict__ gamma, const float* __restrict__ beta,
                       int slot, float cnt, float* __restrict__ g)
{
    float2 mn = load_bn(slot, cnt);
    float ga = gamma[0], be = beta[0];
    for (int j = blockIdx.x * blockDim.x + threadIdx.x; j < NN; j += gridDim.x * blockDim.x) {
        float yv = y[j];
        float acc = 0.f;
#pragma unroll
        for (int c = 0; c < 4; c++) {
            float h = fmaxf(fmaf(yv, w1[c], b1[c]), 0.f);
            float f = fmaf(ga * (h - mn.x), mn.y, be);
            acc = fmaf(w2[c], f, acc);
        }
        g[j] = acc;
    }
}

// ---------------- g_j for concat-block-2 input ----------------
__global__ void prep_gc(const float* __restrict__ u0, const float* __restrict__ u1,
                        const float* __restrict__ wc1, const float* __restrict__ bc1,
                        const float* __restrict__ wc2,
                        const float* __restrict__ gamma, const float* __restrict__ beta,
                        int slot, float cnt, float* __restrict__ g)
{
    float2 mn = load_bn(slot, cnt);
    float ga = gamma[0], be = beta[0];
    for (int j = blockIdx.x * blockDim.x + threadIdx.x; j < NN; j += gridDim.x * blockDim.x) {
        float a = u0[j], b = u1[j];
        float acc = 0.f;
#pragma unroll
        for (int c = 0; c < 4; c++) {
            float h = fmaxf(a * wc1[c] + b * wc1[4 + c] + bc1[c], 0.f);
            float f = fmaf(ga * (h - mn.x), mn.y, be);
            acc = fmaf(wc2[c], f, acc);
        }
        g[j] = acc;
    }
}

// ---------------- out = relu(BN(relu(z + b))) ----------------
__global__ void bn_relu_vec(const float* __restrict__ z, const float* __restrict__ b,
                            const float* __restrict__ gamma, const float* __restrict__ beta,
                            int slot, float* __restrict__ out)
{
    float2 mn = load_bn(slot, (float)NN);
    float ga = gamma[0], be = beta[0], bb = b[0];
    for (int j = blockIdx.x * blockDim.x + threadIdx.x; j < NN; j += gridDim.x * blockDim.x) {
        float h = fmaxf(z[j] + bb, 0.f);
        float f = fmaf(ga * (h - mn.x), mn.y, be);
        out[j] = fmaxf(f, 0.f);
    }
}

// ---------------- launch ----------------
extern "C" void kernel_launch(void* const* d_in, const int* in_sizes, int n_in,
                              void* d_out, int out_size)
{
    const float* x     = (const float*)d_in[0];
    const float* adj   = (const float*)d_in[1];
    const float* w11   = (const float*)d_in[2];
    const float* b11   = (const float*)d_in[3];
    const float* w12   = (const float*)d_in[4];
    const float* b12   = (const float*)d_in[5];
    const float* w21   = (const float*)d_in[6];
    const float* b21   = (const float*)d_in[7];
    const float* w22   = (const float*)d_in[8];
    const float* b22   = (const float*)d_in[9];
    const float* wc1   = (const float*)d_in[10];
    const float* bc1   = (const float*)d_in[11];
    const float* wc2   = (const float*)d_in[12];
    const float* bc2   = (const float*)d_in[13];
    const float* gamma = (const float*)d_in[14];
    const float* beta  = (const float*)d_in[15];
    float* out = (float*)d_out;

    const float* A1  = adj;
    const float* A2  = adj + (size_t)NN * NN;
    const float* A12 = adj + 2 * (size_t)NN * NN;
    const float* F1 = x;
    const float* F2 = x + NN;

    // resolve device-symbol addresses
    static float *py1 = nullptr, *py2, *pg1, *pg2, *pz1, *pz2, *pf0, *pf1, *pu0, *pu1, *pg3, *pz3;
    if (!py1) {
        cudaGetSymbolAddress((void**)&py1, g_y1);
        cudaGetSymbolAddress((void**)&py2, g_y2);
        cudaGetSymbolAddress((void**)&pg1, g_g1);
        cudaGetSymbolAddress((void**)&pg2, g_g2);
        cudaGetSymbolAddress((void**)&pz1, g_z1);
        cudaGetSymbolAddress((void**)&pz2, g_z2);
        cudaGetSymbolAddress((void**)&pf0, g_f0);
        cudaGetSymbolAddress((void**)&pf1, g_f1);
        cudaGetSymbolAddress((void**)&pu0, g_u0);
        cudaGetSymbolAddress((void**)&pu1, g_u1);
        cudaGetSymbolAddress((void**)&pg3, g_g3);
        cudaGetSymbolAddress((void**)&pz3, g_z3);
        cudaFuncSetAttribute(mv_c2, cudaFuncAttributeMaxDynamicSharedMemorySize, 2 * NN * 4);
    }

    dim3 mvGrid2(NN / RPB, 1, 2);
    dim3 mvGrid1(NN / RPB, 1, 1);

    zero_stats_kernel<<<1, 32>>>();

    // ---- block 1 (both branches): y = A @ F ----
    mv_c1<<<mvGrid2, MV_TPB>>>(A1, A2, F1, F2, py1, py2, 0);
    stats_mat4<<<32, 256>>>(py1, w11, b11, 0);
    stats_mat4<<<32, 256>>>(py2, w21, b21, 1);
    prep_g<<<32, 256>>>(py1, w11, b11, w12, gamma, beta, 0, (float)(NN * 4), pg1);
    prep_g<<<32, 256>>>(py2, w21, b21, w22, gamma, beta, 1, (float)(NN * 4), pg2);

    // ---- block 2 (both branches): z = A @ g  (reverse rows: L2 tail reuse) ----
    mv_c1<<<mvGrid2, MV_TPB>>>(A1, A2, pg1, pg2, pz1, pz2, 1);
    stats_vec<<<32, 256>>>(pz1, b12, 2);
    stats_vec<<<32, 256>>>(pz2, b22, 3);
    bn_relu_vec<<<32, 256>>>(pz1, b12, gamma, beta, 2, pf0);
    bn_relu_vec<<<32, 256>>>(pz2, b22, gamma, beta, 3, pf1);

    // ---- concat block 1: u = A12 @ [f0 f1] ----
    mv_c2<<<mvGrid1, MV_TPB, 2 * NN * 4>>>(A12, pf0, pf1, pu0, pu1, 0);
    stats_c1<<<32, 256>>>(pu0, pu1, wc1, bc1, 4);
    prep_gc<<<32, 256>>>(pu0, pu1, wc1, bc1, wc2, gamma, beta, 4, (float)(NN * 4), pg3);

    // ---- concat block 2: z3 = A12 @ g3  (reverse rows) ----
    mv_c1<<<mvGrid1, MV_TPB>>>(A12, A12, pg3, pg3, pz3, pz3, 1);
    stats_vec<<<32, 256>>>(pz3, bc2, 5);
    bn_relu_vec<<<32, 256>>>(pz3, bc2, gamma, beta, 5, out);

    (void)in_sizes; (void)n_in; (void)out_size;
}

// round 2
// speedup vs baseline: 1.0204x; 1.0204x over previous
#include <cuda_runtime.h>

#define NN 8192
#define RPB 8
#define TPB 256
#define K4 (NN / 4 / TPB)   // 8 float4 per thread per row
#define EPS 1e-5f

// ---------------- device scratch ----------------
__device__ float g_stats[12];   // 6 BN stages x (sum, sumsq)
__device__ __align__(16) float g_y1[NN], g_y2[NN];
__device__ __align__(16) float g_z1[NN], g_z2[NN];
__device__ __align__(16) float g_u0[NN], g_u1[NN];
__device__ __align__(16) float g_z3[NN];

__global__ void zero_stats_kernel() {
    if (threadIdx.x < 12) g_stats[threadIdx.x] = 0.f;
}

// row dot product: A[row,:] . xs ; returns full sum valid on lane 0 of each warp
template <bool STREAM>
__device__ __forceinline__ float row_dot(const float* __restrict__ A, int row,
                                         const float4* xs, int tid) {
    const float4* a4 = (const float4*)(A + (size_t)row * NN);
    float acc = 0.f;
#pragma unroll
    for (int k = 0; k < K4; k++) {
        float4 av = STREAM ? __ldcs(a4 + tid + k * TPB) : __ldg(a4 + tid + k * TPB);
        float4 xv = xs[tid + k * TPB];
        acc = fmaf(av.x, xv.x, acc);
        acc = fmaf(av.y, xv.y, acc);
        acc = fmaf(av.z, xv.z, acc);
        acc = fmaf(av.w, xv.w, acc);
    }
#pragma unroll
    for (int o = 16; o > 0; o >>= 1) acc += __shfl_xor_sync(0xffffffffu, acc, o);
    return acc;
}

__device__ __forceinline__ float2 bn_coeffs(int slot, float cnt, float ga, float be) {
    float m = g_stats[2 * slot] / cnt;
    float v = g_stats[2 * slot + 1] / cnt - m * m;
    float scale = ga * rsqrtf(v + EPS);
    return make_float2(scale, be - m * scale);   // f = h*scale + shift
}

// ---- pass 1 (dual via z): y = A @ F ; epilogue: stats over relu(y*w+b) [N,4] -> slot z
__global__ __launch_bounds__(TPB) void mv1(
    const float* __restrict__ Aa, const float* __restrict__ Ab,
    const float* __restrict__ x,
    const float* __restrict__ w11, const float* __restrict__ b11,
    const float* __restrict__ w21, const float* __restrict__ b21)
{
    __shared__ float4 xs[NN / 4];
    __shared__ float red[TPB / 32];
    int z = blockIdx.z;
    const float* A  = z ? Ab : Aa;
    const float* xp = x + z * NN;
    float*       yp = z ? g_y2 : g_y1;
    const float* w  = z ? w21 : w11;
    const float* b  = z ? b21 : b11;
    int tid = threadIdx.x;
    const float4* x4 = (const float4*)xp;
#pragma unroll
    for (int k = 0; k < K4; k++) xs[tid + k * TPB] = x4[tid + k * TPB];
    __syncthreads();

    float w0 = w[0], w1 = w[1], w2 = w[2], w3 = w[3];
    float b0 = b[0], b1 = b[1], b2 = b[2], b3 = b[3];
    float s = 0.f, s2 = 0.f;
    int rbase = blockIdx.x * RPB;
    for (int r = 0; r < RPB; r++) {
        int row = rbase + r;
        float acc = row_dot<false>(A, row, xs, tid);
        if ((tid & 31) == 0) red[tid >> 5] = acc;
        __syncthreads();
        if (tid == 0) {
            float t = 0.f;
#pragma unroll
            for (int i = 0; i < TPB / 32; i++) t += red[i];
            yp[row] = t;
            float v0 = fmaxf(fmaf(t, w0, b0), 0.f), v1 = fmaxf(fmaf(t, w1, b1), 0.f);
            float v2 = fmaxf(fmaf(t, w2, b2), 0.f), v3 = fmaxf(fmaf(t, w3, b3), 0.f);
            s  += v0 + v1 + v2 + v3;
            s2 += v0 * v0 + v1 * v1 + v2 * v2 + v3 * v3;
        }
        __syncthreads();
    }
    if (tid == 0) { atomicAdd(&g_stats[2 * z], s); atomicAdd(&g_stats[2 * z + 1], s2); }
}

// ---- pass 2 (dual): g computed in prologue from y (slot z), z = A @ g reversed;
//      epilogue: stats over relu(z+b) -> slot 2+z
__global__ __launch_bounds__(TPB) void mv2(
    const float* __restrict__ Aa, const float* __restrict__ Ab,
    const float* __restrict__ w11, const float* __restrict__ b11, const float* __restrict__ w12,
    const float* __restrict__ w21, const float* __restrict__ b21, const float* __restrict__ w22,
    const float* __restrict__ b12, const float* __restrict__ b22,
    const float* __restrict__ gamma, const float* __restrict__ beta)
{
    __shared__ float4 xs[NN / 4];
    __shared__ float red[TPB / 32];
    int z = blockIdx.z;
    const float* A   = z ? Ab : Aa;
    const float* y   = z ? g_y2 : g_y1;
    float*       zp  = z ? g_z2 : g_z1;
    const float* w1v = z ? w21 : w11;
    const float* b1v = z ? b21 : b11;
    const float* w2v = z ? w22 : w12;
    float bb = z ? b22[0] : b12[0];
    float ga = gamma[0], be = beta[0];
    float2 c = bn_coeffs(z, (float)(NN * 4), ga, be);
    float wa0 = w1v[0], wa1 = w1v[1], wa2 = w1v[2], wa3 = w1v[3];
    float ba0 = b1v[0], ba1 = b1v[1], ba2 = b1v[2], ba3 = b1v[3];
    float wb0 = w2v[0], wb1 = w2v[1], wb2 = w2v[2], wb3 = w2v[3];
    int tid = threadIdx.x;
    const float4* y4 = (const float4*)y;
#pragma unroll
    for (int k = 0; k < K4; k++) {
        float4 yv = y4[tid + k * TPB];
        float4 gv;
        float* pi = (float*)&yv;
        float* po = (float*)&gv;
#pragma unroll
        for (int e = 0; e < 4; e++) {
            float yy = pi[e];
            float h0 = fmaxf(fmaf(yy, wa0, ba0), 0.f);
            float h1 = fmaxf(fmaf(yy, wa1, ba1), 0.f);
            float h2 = fmaxf(fmaf(yy, wa2, ba2), 0.f);
            float h3 = fmaxf(fmaf(yy, wa3, ba3), 0.f);
            float a = wb0 * fmaf(h0, c.x, c.y) + wb1 * fmaf(h1, c.x, c.y)
                    + wb2 * fmaf(h2, c.x, c.y) + wb3 * fmaf(h3, c.x, c.y);
            po[e] = a;
        }
        xs[tid + k * TPB] = gv;
    }
    __syncthreads();

    float s = 0.f, s2 = 0.f;
    int rbase = blockIdx.x * RPB;
    for (int r = 0; r < RPB; r++) {
        int row = NN - 1 - (rbase + r);     // reverse: reuse L2 tail of pass 1
        float acc = row_dot<true>(A, row, xs, tid);
        if ((tid & 31) == 0) red[tid >> 5] = acc;
        __syncthreads();
        if (tid == 0) {
            float t = 0.f;
#pragma unroll
            for (int i = 0; i < TPB / 32; i++) t += red[i];
            zp[row] = t;
            float v = fmaxf(t + bb, 0.f);
            s += v; s2 += v * v;
        }
        __syncthreads();
    }
    if (tid == 0) { atomicAdd(&g_stats[2 * (2 + z)], s); atomicAdd(&g_stats[2 * (2 + z) + 1], s2); }
}

// ---- pass 3: f0,f1 computed from z1,z2 (slots 2,3); (u0,u1) = A12 @ [f0 f1];
//      epilogue: stats of concat-block-1 activations -> slot 4
__global__ __launch_bounds__(TPB) void mv3(
    const float* __restrict__ A,
    const float* __restrict__ b12, const float* __restrict__ b22,
    const float* __restrict__ wc1, const float* __restrict__ bc1,
    const float* __restrict__ gamma, const float* __restrict__ beta)
{
    extern __shared__ float shd[];
    float4* xs0 = (float4*)shd;
    float4* xs1 = (float4*)(shd + NN);
    __shared__ float red[2][TPB / 32];
    float ga = gamma[0], be = beta[0];
    float2 c2 = bn_coeffs(2, (float)NN, ga, be);
    float2 c3 = bn_coeffs(3, (float)NN, ga, be);
    float bb1 = b12[0], bb2 = b22[0];
    int tid = threadIdx.x;
    const float4* z14 = (const float4*)g_z1;
    const float4* z24 = (const float4*)g_z2;
#pragma unroll
    for (int k = 0; k < K4; k++) {
        float4 a = z14[tid + k * TPB];
        float4 b = z24[tid + k * TPB];
        float* pa = (float*)&a; float* pb = (float*)&b;
#pragma unroll
        for (int e = 0; e < 4; e++) {
            pa[e] = fmaxf(fmaf(fmaxf(pa[e] + bb1, 0.f), c2.x, c2.y), 0.f);
            pb[e] = fmaxf(fmaf(fmaxf(pb[e] + bb2, 0.f), c3.x, c3.y), 0.f);
        }
        xs0[tid + k * TPB] = a;
        xs1[tid + k * TPB] = b;
    }
    __syncthreads();

    float wA0 = wc1[0], wA1 = wc1[1], wA2 = wc1[2], wA3 = wc1[3];
    float wB0 = wc1[4], wB1 = wc1[5], wB2 = wc1[6], wB3 = wc1[7];
    float bc0 = bc1[0], bcv1 = bc1[1], bc2v = bc1[2], bc3 = bc1[3];
    float s = 0.f, s2 = 0.f;
    int rbase = blockIdx.x * RPB;
    for (int r = 0; r < RPB; r++) {
        int row = rbase + r;
        const float4* a4 = (const float4*)(A + (size_t)row * NN);
        float acc0 = 0.f, acc1 = 0.f;
#pragma unroll
        for (int k = 0; k < K4; k++) {
            float4 av = __ldg(a4 + tid + k * TPB);
            float4 v0 = xs0[tid + k * TPB];
            float4 v1 = xs1[tid + k * TPB];
            acc0 = fmaf(av.x, v0.x, acc0); acc0 = fmaf(av.y, v0.y, acc0);
            acc0 = fmaf(av.z, v0.z, acc0); acc0 = fmaf(av.w, v0.w, acc0);
            acc1 = fmaf(av.x, v1.x, acc1); acc1 = fmaf(av.y, v1.y, acc1);
            acc1 = fmaf(av.z, v1.z, acc1); acc1 = fmaf(av.w, v1.w, acc1);
        }
#pragma unroll
        for (int o = 16; o > 0; o >>= 1) {
            acc0 += __shfl_xor_sync(0xffffffffu, acc0, o);
            acc1 += __shfl_xor_sync(0xffffffffu, acc1, o);
        }
        if ((tid & 31) == 0) { red[0][tid >> 5] = acc0; red[1][tid >> 5] = acc1; }
        __syncthreads();
        if (tid == 0) {
            float t0 = 0.f, t1 = 0.f;
#pragma unroll
            for (int i = 0; i < TPB / 32; i++) { t0 += red[0][i]; t1 += red[1][i]; }
            g_u0[row] = t0;
            g_u1[row] = t1;
            float v0 = fmaxf(t0 * wA0 + t1 * wB0 + bc0, 0.f);
            float v1 = fmaxf(t0 * wA1 + t1 * wB1 + bcv1, 0.f);
            float v2 = fmaxf(t0 * wA2 + t1 * wB2 + bc2v, 0.f);
            float v3 = fmaxf(t0 * wA3 + t1 * wB3 + bc3, 0.f);
            s  += v0 + v1 + v2 + v3;
            s2 += v0 * v0 + v1 * v1 + v2 * v2 + v3 * v3;
        }
        __syncthreads();
    }
    if (tid == 0) { atomicAdd(&g_stats[8], s); atomicAdd(&g_stats[9], s2); }
}

// ---- pass 4: g3 from (u0,u1) (slot 4); z3 = A12 @ g3 reversed; stats relu(z3+bc2) -> slot 5
__global__ __launch_bounds__(TPB) void mv4(
    const float* __restrict__ A,
    const float* __restrict__ wc1, const float* __restrict__ bc1,
    const float* __restrict__ wc2, const float* __restrict__ bc2,
    const float* __restrict__ gamma, const float* __restrict__ beta)
{
    __shared__ float4 xs[NN / 4];
    __shared__ float red[TPB / 32];
    float ga = gamma[0], be = beta[0];
    float2 c = bn_coeffs(4, (float)(NN * 4), ga, be);
    float wA0 = wc1[0], wA1 = wc1[1], wA2 = wc1[2], wA3 = wc1[3];
    float wB0 = wc1[4], wB1 = wc1[5], wB2 = wc1[6], wB3 = wc1[7];
    float bc0 = bc1[0], bcv1 = bc1[1], bc2v = bc1[2], bc3 = bc1[3];
    float wo0 = wc2[0], wo1 = wc2[1], wo2 = wc2[2], wo3 = wc2[3];
    float bb = bc2[0];
    int tid = threadIdx.x;
    const float4* u04 = (const float4*)g_u0;
    const float4* u14 = (const float4*)g_u1;
#pragma unroll
    for (int k = 0; k < K4; k++) {
        float4 a = u04[tid + k * TPB];
        float4 b = u14[tid + k * TPB];
        float4 gv;
        float* pa = (float*)&a; float* pb = (float*)&b; float* po = (float*)&gv;
#pragma unroll
        for (int e = 0; e < 4; e++) {
            float t0 = pa[e], t1 = pb[e];
            float h0 = fmaxf(t0 * wA0 + t1 * wB0 + bc0, 0.f);
            float h1 = fmaxf(t0 * wA1 + t1 * wB1 + bcv1, 0.f);
            float h2 = fmaxf(t0 * wA2 + t1 * wB2 + bc2v, 0.f);
            float h3 = fmaxf(t0 * wA3 + t1 * wB3 + bc3, 0.f);
            po[e] = wo0 * fmaf(h0, c.x, c.y) + wo1 * fmaf(h1, c.x, c.y)
                  + wo2 * fmaf(h2, c.x, c.y) + wo3 * fmaf(h3, c.x, c.y);
        }
        xs[tid + k * TPB] = gv;
    }
    __syncthreads();

    float s = 0.f, s2 = 0.f;
    int rbase = blockIdx.x * RPB;
    for (int r = 0; r < RPB; r++) {
        int row = NN - 1 - (rbase + r);
        float acc = row_dot<true>(A, row, xs, tid);
        if ((tid & 31) == 0) red[tid >> 5] = acc;
        __syncthreads();
        if (tid == 0) {
            float t = 0.f;
#pragma unroll
            for (int i = 0; i < TPB / 32; i++) t += red[i];
            g_z3[row] = t;
            float v = fmaxf(t + bb, 0.f);
            s += v; s2 += v * v;
        }
        __syncthreads();
    }
    if (tid == 0) { atomicAdd(&g_stats[10], s); atomicAdd(&g_stats[11], s2); }
}

// ---- final: out = relu(BN(relu(z3 + bc2))) with slot 5
__global__ void final_kernel(const float* __restrict__ bc2,
                             const float* __restrict__ gamma, const float* __restrict__ beta,
                             float* __restrict__ out)
{
    float2 c = bn_coeffs(5, (float)NN, gamma[0], beta[0]);
    float bb = bc2[0];
    for (int j = blockIdx.x * blockDim.x + threadIdx.x; j < NN; j += gridDim.x * blockDim.x) {
        float h = fmaxf(g_z3[j] + bb, 0.f);
        out[j] = fmaxf(fmaf(h, c.x, c.y), 0.f);
    }
}

// ---------------- launch ----------------
extern "C" void kernel_launch(void* const* d_in, const int* in_sizes, int n_in,
                              void* d_out, int out_size)
{
    const float* x     = (const float*)d_in[0];
    const float* adj   = (const float*)d_in[1];
    const float* w11   = (const float*)d_in[2];
    const float* b11   = (const float*)d_in[3];
    const float* w12   = (const float*)d_in[4];
    const float* b12   = (const float*)d_in[5];
    const float* w21   = (const float*)d_in[6];
    const float* b21   = (const float*)d_in[7];
    const float* w22   = (const float*)d_in[8];
    const float* b22   = (const float*)d_in[9];
    const float* wc1   = (const float*)d_in[10];
    const float* bc1   = (const float*)d_in[11];
    const float* wc2   = (const float*)d_in[12];
    const float* bc2   = (const float*)d_in[13];
    const float* gamma = (const float*)d_in[14];
    const float* beta  = (const float*)d_in[15];
    float* out = (float*)d_out;

    const float* A1  = adj;
    const float* A2  = adj + (size_t)NN * NN;
    const float* A12 = adj + 2 * (size_t)NN * NN;

    static bool init = false;
    if (!init) {
        cudaFuncSetAttribute(mv3, cudaFuncAttributeMaxDynamicSharedMemorySize, 2 * NN * 4);
        init = true;
    }

    dim3 g2(NN / RPB, 1, 2);
    dim3 g1(NN / RPB, 1, 1);

    zero_stats_kernel<<<1, 32>>>();
    mv1<<<g2, TPB>>>(A1, A2, x, w11, b11, w21, b21);
    mv2<<<g2, TPB>>>(A1, A2, w11, b11, w12, w21, b21, w22, b12, b22, gamma, beta);
    mv3<<<g1, TPB, 2 * NN * 4>>>(A12, b12, b22, wc1, bc1, gamma, beta);
    mv4<<<g1, TPB>>>(A12, wc1, bc1, wc2, bc2, gamma, beta);
    final_kernel<<<32, 256>>>(bc2, gamma, beta, out);

    (void)in_sizes; (void)n_in; (void)out_size;
}

// round 3
// speedup vs baseline: 1.0884x; 1.0667x over previous
#include <cuda_runtime.h>

#define NN 8192
#define TPB 256
#define NWARP (TPB / 32)
#define K4 (NN / 4 / TPB)     // 8 float4 per thread for prologue staging
#define KW (NN / 4 / 32)      // 64 float4 per lane per row
#define EPS 1e-5f

// ---------------- device scratch ----------------
__device__ float g_stats[12];   // 6 BN stages x (sum, sumsq)
__device__ __align__(16) float g_y1[NN], g_y2[NN];
__device__ __align__(16) float g_z1[NN], g_z2[NN];
__device__ __align__(16) float g_u0[NN], g_u1[NN];
__device__ __align__(16) float g_z3[NN];

__global__ void zero_stats_kernel() {
    if (threadIdx.x < 12) g_stats[threadIdx.x] = 0.f;
}

__device__ __forceinline__ float2 bn_coeffs(int slot, float cnt, float ga, float be) {
    float m = g_stats[2 * slot] / cnt;
    float v = g_stats[2 * slot + 1] / cnt - m * m;
    float scale = ga * rsqrtf(v + EPS);
    return make_float2(scale, be - m * scale);   // f = h*scale + shift
}

// warp-cooperative row dot: one warp owns the whole row. 4 accumulator chains.
template <bool STREAM>
__device__ __forceinline__ float warp_row_dot(const float* __restrict__ A, int row,
                                              const float4* xs, int lane) {
    const float4* a4 = (const float4*)(A + (size_t)row * NN);
    float acc0 = 0.f, acc1 = 0.f, acc2 = 0.f, acc3 = 0.f;
#pragma unroll
    for (int k = 0; k < KW; k += 4) {
        float4 a0 = STREAM ? __ldcs(a4 + lane + (k + 0) * 32) : __ldg(a4 + lane + (k + 0) * 32);
        float4 a1 = STREAM ? __ldcs(a4 + lane + (k + 1) * 32) : __ldg(a4 + lane + (k + 1) * 32);
        float4 a2 = STREAM ? __ldcs(a4 + lane + (k + 2) * 32) : __ldg(a4 + lane + (k + 2) * 32);
        float4 a3 = STREAM ? __ldcs(a4 + lane + (k + 3) * 32) : __ldg(a4 + lane + (k + 3) * 32);
        float4 x0 = xs[lane + (k + 0) * 32];
        float4 x1 = xs[lane + (k + 1) * 32];
        float4 x2 = xs[lane + (k + 2) * 32];
        float4 x3 = xs[lane + (k + 3) * 32];
        acc0 = fmaf(a0.x, x0.x, acc0); acc0 = fmaf(a0.y, x0.y, acc0);
        acc0 = fmaf(a0.z, x0.z, acc0); acc0 = fmaf(a0.w, x0.w, acc0);
        acc1 = fmaf(a1.x, x1.x, acc1); acc1 = fmaf(a1.y, x1.y, acc1);
        acc1 = fmaf(a1.z, x1.z, acc1); acc1 = fmaf(a1.w, x1.w, acc1);
        acc2 = fmaf(a2.x, x2.x, acc2); acc2 = fmaf(a2.y, x2.y, acc2);
        acc2 = fmaf(a2.z, x2.z, acc2); acc2 = fmaf(a2.w, x2.w, acc2);
        acc3 = fmaf(a3.x, x3.x, acc3); acc3 = fmaf(a3.y, x3.y, acc3);
        acc3 = fmaf(a3.z, x3.z, acc3); acc3 = fmaf(a3.w, x3.w, acc3);
    }
    float acc = (acc0 + acc1) + (acc2 + acc3);
#pragma unroll
    for (int o = 16; o > 0; o >>= 1) acc += __shfl_xor_sync(0xffffffffu, acc, o);
    return acc;   // valid on all lanes
}

// block-level stats flush: each warp's lane0 deposited (s,s2) in sred
__device__ __forceinline__ void flush_stats(float s, float s2, float (*sred)[2],
                                            int lane, int wid, int tid, float* dst) {
    if (lane == 0) { sred[wid][0] = s; sred[wid][1] = s2; }
    __syncthreads();
    if (tid == 0) {
        float a = 0.f, b = 0.f;
#pragma unroll
        for (int i = 0; i < NWARP; i++) { a += sred[i][0]; b += sred[i][1]; }
        atomicAdd(dst, a);
        atomicAdd(dst + 1, b);
    }
}

// ---- pass 1 (dual via z): y = A @ F ; stats over relu(y*w+b) [N,4] -> slot z
__global__ __launch_bounds__(TPB) void mv1(
    const float* __restrict__ Aa, const float* __restrict__ Ab,
    const float* __restrict__ x,
    const float* __restrict__ w11, const float* __restrict__ b11,
    const float* __restrict__ w21, const float* __restrict__ b21)
{
    __shared__ float4 xs[NN / 4];
    __shared__ float sred[NWARP][2];
    int z = blockIdx.z;
    const float* A  = z ? Ab : Aa;
    const float* xp = x + z * NN;
    float*       yp = z ? g_y2 : g_y1;
    const float* w  = z ? w21 : w11;
    const float* b  = z ? b21 : b11;
    int tid = threadIdx.x, lane = tid & 31, wid = tid >> 5;
    const float4* x4 = (const float4*)xp;
#pragma unroll
    for (int k = 0; k < K4; k++) xs[tid + k * TPB] = x4[tid + k * TPB];
    __syncthreads();

    int row = blockIdx.x * NWARP + wid;
    float t = warp_row_dot<false>(A, row, xs, lane);

    float s = 0.f, s2 = 0.f;
    if (lane == 0) {
        yp[row] = t;
        float v0 = fmaxf(fmaf(t, w[0], b[0]), 0.f), v1 = fmaxf(fmaf(t, w[1], b[1]), 0.f);
        float v2 = fmaxf(fmaf(t, w[2], b[2]), 0.f), v3 = fmaxf(fmaf(t, w[3], b[3]), 0.f);
        s  = v0 + v1 + v2 + v3;
        s2 = v0 * v0 + v1 * v1 + v2 * v2 + v3 * v3;
    }
    flush_stats(s, s2, sred, lane, wid, tid, &g_stats[2 * z]);
}

// ---- pass 2 (dual): prologue builds g from y (slot z); z = A @ g reversed;
//      stats over relu(z+b) -> slot 2+z
__global__ __launch_bounds__(TPB) void mv2(
    const float* __restrict__ Aa, const float* __restrict__ Ab,
    const float* __restrict__ w11, const float* __restrict__ b11, const float* __restrict__ w12,
    const float* __restrict__ w21, const float* __restrict__ b21, const float* __restrict__ w22,
    const float* __restrict__ b12, const float* __restrict__ b22,
    const float* __restrict__ gamma, const float* __restrict__ beta)
{
    __shared__ float4 xs[NN / 4];
    __shared__ float sred[NWARP][2];
    int z = blockIdx.z;
    const float* A   = z ? Ab : Aa;
    const float* y   = z ? g_y2 : g_y1;
    float*       zp  = z ? g_z2 : g_z1;
    const float* w1v = z ? w21 : w11;
    const float* b1v = z ? b21 : b11;
    const float* w2v = z ? w22 : w12;
    float bb = z ? b22[0] : b12[0];
    float2 c = bn_coeffs(z, (float)(NN * 4), gamma[0], beta[0]);
    float wa0 = w1v[0], wa1 = w1v[1], wa2 = w1v[2], wa3 = w1v[3];
    float ba0 = b1v[0], ba1 = b1v[1], ba2 = b1v[2], ba3 = b1v[3];
    float wb0 = w2v[0], wb1 = w2v[1], wb2 = w2v[2], wb3 = w2v[3];
    int tid = threadIdx.x, lane = tid & 31, wid = tid >> 5;
    const float4* y4 = (const float4*)y;
#pragma unroll
    for (int k = 0; k < K4; k++) {
        float4 yv = y4[tid + k * TPB];
        float4 gv;
        float* pi = (float*)&yv; float* po = (float*)&gv;
#pragma unroll
        for (int e = 0; e < 4; e++) {
            float yy = pi[e];
            float h0 = fmaxf(fmaf(yy, wa0, ba0), 0.f);
            float h1 = fmaxf(fmaf(yy, wa1, ba1), 0.f);
            float h2 = fmaxf(fmaf(yy, wa2, ba2), 0.f);
            float h3 = fmaxf(fmaf(yy, wa3, ba3), 0.f);
            po[e] = wb0 * fmaf(h0, c.x, c.y) + wb1 * fmaf(h1, c.x, c.y)
                  + wb2 * fmaf(h2, c.x, c.y) + wb3 * fmaf(h3, c.x, c.y);
        }
        xs[tid + k * TPB] = gv;
    }
    __syncthreads();

    int row = NN - 1 - (blockIdx.x * NWARP + wid);   // reverse: L2 tail reuse
    float t = warp_row_dot<true>(A, row, xs, lane);

    float s = 0.f, s2 = 0.f;
    if (lane == 0) {
        zp[row] = t;
        float v = fmaxf(t + bb, 0.f);
        s = v; s2 = v * v;
    }
    flush_stats(s, s2, sred, lane, wid, tid, &g_stats[2 * (2 + z)]);
}

// ---- pass 3: prologue builds f0,f1 (slots 2,3); (u0,u1) = A12 @ [f0 f1];
//      stats of concat-block-1 activations -> slot 4
__global__ __launch_bounds__(TPB) void mv3(
    const float* __restrict__ A,
    const float* __restrict__ b12, const float* __restrict__ b22,
    const float* __restrict__ wc1, const float* __restrict__ bc1,
    const float* __restrict__ gamma, const float* __restrict__ beta)
{
    extern __shared__ float shd[];
    float4* xs0 = (float4*)shd;
    float4* xs1 = (float4*)(shd + NN);
    __shared__ float sred[NWARP][2];
    float ga = gamma[0], be = beta[0];
    float2 c2 = bn_coeffs(2, (float)NN, ga, be);
    float2 c3 = bn_coeffs(3, (float)NN, ga, be);
    float bb1 = b12[0], bb2 = b22[0];
    int tid = threadIdx.x, lane = tid & 31, wid = tid >> 5;
    const float4* z14 = (const float4*)g_z1;
    const float4* z24 = (const float4*)g_z2;
#pragma unroll
    for (int k = 0; k < K4; k++) {
        float4 a = z14[tid + k * TPB];
        float4 b = z24[tid + k * TPB];
        float* pa = (float*)&a; float* pb = (float*)&b;
#pragma unroll
        for (int e = 0; e < 4; e++) {
            pa[e] = fmaxf(fmaf(fmaxf(pa[e] + bb1, 0.f), c2.x, c2.y), 0.f);
            pb[e] = fmaxf(fmaf(fmaxf(pb[e] + bb2, 0.f), c3.x, c3.y), 0.f);
        }
        xs0[tid + k * TPB] = a;
        xs1[tid + k * TPB] = b;
    }
    __syncthreads();

    int row = blockIdx.x * NWARP + wid;
    const float4* a4 = (const float4*)(A + (size_t)row * NN);
    float p00 = 0.f, p01 = 0.f, p10 = 0.f, p11 = 0.f;
#pragma unroll
    for (int k = 0; k < KW; k += 2) {
        float4 a0 = __ldg(a4 + lane + (k + 0) * 32);
        float4 a1 = __ldg(a4 + lane + (k + 1) * 32);
        float4 u0 = xs0[lane + (k + 0) * 32];
        float4 u1 = xs0[lane + (k + 1) * 32];
        float4 v0 = xs1[lane + (k + 0) * 32];
        float4 v1 = xs1[lane + (k + 1) * 32];
        p00 = fmaf(a0.x, u0.x, p00); p00 = fmaf(a0.y, u0.y, p00);
        p00 = fmaf(a0.z, u0.z, p00); p00 = fmaf(a0.w, u0.w, p00);
        p01 = fmaf(a1.x, u1.x, p01); p01 = fmaf(a1.y, u1.y, p01);
        p01 = fmaf(a1.z, u1.z, p01); p01 = fmaf(a1.w, u1.w, p01);
        p10 = fmaf(a0.x, v0.x, p10); p10 = fmaf(a0.y, v0.y, p10);
        p10 = fmaf(a0.z, v0.z, p10); p10 = fmaf(a0.w, v0.w, p10);
        p11 = fmaf(a1.x, v1.x, p11); p11 = fmaf(a1.y, v1.y, p11);
        p11 = fmaf(a1.z, v1.z, p11); p11 = fmaf(a1.w, v1.w, p11);
    }
    float t0 = p00 + p01, t1 = p10 + p11;
#pragma unroll
    for (int o = 16; o > 0; o >>= 1) {
        t0 += __shfl_xor_sync(0xffffffffu, t0, o);
        t1 += __shfl_xor_sync(0xffffffffu, t1, o);
    }

    float s = 0.f, s2 = 0.f;
    if (lane == 0) {
        g_u0[row] = t0;
        g_u1[row] = t1;
        float v0 = fmaxf(t0 * wc1[0] + t1 * wc1[4] + bc1[0], 0.f);
        float v1 = fmaxf(t0 * wc1[1] + t1 * wc1[5] + bc1[1], 0.f);
        float v2 = fmaxf(t0 * wc1[2] + t1 * wc1[6] + bc1[2], 0.f);
        float v3 = fmaxf(t0 * wc1[3] + t1 * wc1[7] + bc1[3], 0.f);
        s  = v0 + v1 + v2 + v3;
        s2 = v0 * v0 + v1 * v1 + v2 * v2 + v3 * v3;
    }
    flush_stats(s, s2, sred, lane, wid, tid, &g_stats[8]);
}

// ---- pass 4: prologue builds g3 from (u0,u1) (slot 4); z3 = A12 @ g3 reversed;
//      stats relu(z3+bc2) -> slot 5
__global__ __launch_bounds__(TPB) void mv4(
    const float* __restrict__ A,
    const float* __restrict__ wc1, const float* __restrict__ bc1,
    const float* __restrict__ wc2, const float* __restrict__ bc2,
    const float* __restrict__ gamma, const float* __restrict__ beta)
{
    __shared__ float4 xs[NN / 4];
    __shared__ float sred[NWARP][2];
    float2 c = bn_coeffs(4, (float)(NN * 4), gamma[0], beta[0]);
    float wA0 = wc1[0], wA1 = wc1[1], wA2 = wc1[2], wA3 = wc1[3];
    float wB0 = wc1[4], wB1 = wc1[5], wB2 = wc1[6], wB3 = wc1[7];
    float bc0 = bc1[0], bcv1 = bc1[1], bc2v = bc1[2], bc3 = bc1[3];
    float wo0 = wc2[0], wo1 = wc2[1], wo2 = wc2[2], wo3 = wc2[3];
    float bb = bc2[0];
    int tid = threadIdx.x, lane = tid & 31, wid = tid >> 5;
    const float4* u04 = (const float4*)g_u0;
    const float4* u14 = (const float4*)g_u1;
#pragma unroll
    for (int k = 0; k < K4; k++) {
        float4 a = u04[tid + k * TPB];
        float4 b = u14[tid + k * TPB];
        float4 gv;
        float* pa = (float*)&a; float* pb = (float*)&b; float* po = (float*)&gv;
#pragma unroll
        for (int e = 0; e < 4; e++) {
            float t0 = pa[e], t1 = pb[e];
            float h0 = fmaxf(t0 * wA0 + t1 * wB0 + bc0, 0.f);
            float h1 = fmaxf(t0 * wA1 + t1 * wB1 + bcv1, 0.f);
            float h2 = fmaxf(t0 * wA2 + t1 * wB2 + bc2v, 0.f);
            float h3 = fmaxf(t0 * wA3 + t1 * wB3 + bc3, 0.f);
            po[e] = wo0 * fmaf(h0, c.x, c.y) + wo1 * fmaf(h1, c.x, c.y)
                  + wo2 * fmaf(h2, c.x, c.y) + wo3 * fmaf(h3, c.x, c.y);
        }
        xs[tid + k * TPB] = gv;
    }
    __syncthreads();

    int row = NN - 1 - (blockIdx.x * NWARP + wid);
    float t = warp_row_dot<true>(A, row, xs, lane);

    float s = 0.f, s2 = 0.f;
    if (lane == 0) {
        g_z3[row] = t;
        float v = fmaxf(t + bb, 0.f);
        s = v; s2 = v * v;
    }
    flush_stats(s, s2, sred, lane, wid, tid, &g_stats[10]);
}

// ---- final: out = relu(BN(relu(z3 + bc2))) with slot 5
__global__ void final_kernel(const float* __restrict__ bc2,
                             const float* __restrict__ gamma, const float* __restrict__ beta,
                             float* __restrict__ out)
{
    float2 c = bn_coeffs(5, (float)NN, gamma[0], beta[0]);
    float bb = bc2[0];
    for (int j = blockIdx.x * blockDim.x + threadIdx.x; j < NN; j += gridDim.x * blockDim.x) {
        float h = fmaxf(g_z3[j] + bb, 0.f);
        out[j] = fmaxf(fmaf(h, c.x, c.y), 0.f);
    }
}

// ---------------- launch ----------------
extern "C" void kernel_launch(void* const* d_in, const int* in_sizes, int n_in,
                              void* d_out, int out_size)
{
    const float* x     = (const float*)d_in[0];
    const float* adj   = (const float*)d_in[1];
    const float* w11   = (const float*)d_in[2];
    const float* b11   = (const float*)d_in[3];
    const float* w12   = (const float*)d_in[4];
    const float* b12   = (const float*)d_in[5];
    const float* w21   = (const float*)d_in[6];
    const float* b21   = (const float*)d_in[7];
    const float* w22   = (const float*)d_in[8];
    const float* b22   = (const float*)d_in[9];
    const float* wc1   = (const float*)d_in[10];
    const float* bc1   = (const float*)d_in[11];
    const float* wc2   = (const float*)d_in[12];
    const float* bc2   = (const float*)d_in[13];
    const float* gamma = (const float*)d_in[14];
    const float* beta  = (const float*)d_in[15];
    float* out = (float*)d_out;

    const float* A1  = adj;
    const float* A2  = adj + (size_t)NN * NN;
    const float* A12 = adj + 2 * (size_t)NN * NN;

    static bool init = false;
    if (!init) {
        cudaFuncSetAttribute(mv3, cudaFuncAttributeMaxDynamicSharedMemorySize, 2 * NN * 4);
        init = true;
    }

    dim3 g2(NN / NWARP, 1, 2);
    dim3 g1(NN / NWARP, 1, 1);

    zero_stats_kernel<<<1, 32>>>();
    mv1<<<g2, TPB>>>(A1, A2, x, w11, b11, w21, b21);
    mv2<<<g2, TPB>>>(A1, A2, w11, b11, w12, w21, b21, w22, b12, b22, gamma, beta);
    mv3<<<g1, TPB, 2 * NN * 4>>>(A12, b12, b22, wc1, bc1, gamma, beta);
    mv4<<<g1, TPB>>>(A12, wc1, bc1, wc2, bc2, gamma, beta);
    final_kernel<<<32, 256>>>(bc2, gamma, beta, out);

    (void)in_sizes; (void)n_in; (void)out_size;
}